// round 11
// baseline (speedup 1.0000x reference)
#include <cuda_runtime.h>

// Problem constants (shapes fixed by the dataset).
#define H_DIM 128
#define E_MAX 625000
#define N_MAX 100096

// Scratch (device globals — no allocations allowed).
__device__ __align__(16) float g_gate[E_MAX];
__device__ float        g_rowsum[N_MAX];
__device__ unsigned int g_h1[2048];
__device__ unsigned int g_cand[E_MAX];     // gate-bit patterns in the sel1 bin
__device__ unsigned int g_candCnt;
__device__ unsigned int g_done1, g_done2;  // last-block-done counters
__device__ unsigned int g_sel1, g_kRem;
__device__ unsigned int g_uT;              // final 32-bit keep threshold
__device__ int          g_idx32;           // 1 if edge_index is int32, 0 if int64

// Index fetch that works for either dtype (uniform branch on device flag).
__device__ __forceinline__ int edge_idx(const void* ei, int is32, long long pos) {
    if (is32) return ((const int*)ei)[pos];
    return (int)(((const long long*)ei)[pos]);
}

// ---------------------------------------------------------------------------
// Block-wide (256 threads) descending radix select over B bins (B = 256*chunk,
// chunk <= 8). hist holds counts in smem. Finds bin containing the k-th
// largest (1-based, counting from the top bin down); writes sel & residual k.
// ---------------------------------------------------------------------------
__device__ void block_suffix_select(const unsigned int* hist, int B,
                                    unsigned int k,
                                    unsigned int* scan,          // smem [256]
                                    volatile unsigned int* outSel,
                                    volatile unsigned int* outK) {
    int t = threadIdx.x;
    int chunk = B >> 8;
    unsigned int loc[8];
    unsigned int s = 0;
    for (int j = 0; j < chunk; j++) { loc[j] = hist[t * chunk + j]; s += loc[j]; }
    scan[t] = s;
    __syncthreads();
    // inclusive suffix scan over 256 chunk-sums
    for (int off = 1; off < 256; off <<= 1) {
        unsigned int v   = scan[t];
        unsigned int add = (t + off < 256) ? scan[t + off] : 0u;
        __syncthreads();
        scan[t] = v + add;
        __syncthreads();
    }
    unsigned int run = (t + 1 < 256) ? scan[t + 1] : 0u;   // suffix after my chunk
    for (int j = chunk - 1; j >= 0; j--) {
        unsigned int nxt = run + loc[j];
        if (run < k && nxt >= k) {          // exactly one (t,j) straddles k
            *outSel = (unsigned int)(t * chunk + j);
            *outK   = k - run;
        }
        run = nxt;
    }
    __syncthreads();
}

// ---------------------------------------------------------------------------
// K0: zero h1 + counters (graph replays reuse state), detect edge_index dtype.
// int32 read as int64 gives idx0 + idx1*2^32, out of [0,N) w.p. ~1 per sample.
// ---------------------------------------------------------------------------
__global__ void init_kernel(const void* ei, int N) {
    int i = blockIdx.x * blockDim.x + threadIdx.x;
    if (i < 2048) g_h1[i] = 0u;
    if (i == 0) { g_candCnt = 0u; g_done1 = 0u; g_done2 = 0u; }

    if (blockIdx.x == 0) {               // block-uniform branch: sync is legal
        const long long* p = (const long long*)ei;
        int bad = 0;
        for (int j = threadIdx.x; j < 1024; j += blockDim.x) {
            long long v = p[j];
            if (v < 0 || v >= (long long)N) bad = 1;
        }
        int any = __syncthreads_or(bad);
        if (threadIdx.x == 0) g_idx32 = any ? 1 : 0;
    }
}

// ---------------------------------------------------------------------------
// K1: gate computation, 8 lanes per edge (4 edges/warp), level-1 histogram,
// rowsum zeroing (surplus threads), and fused level-1 select in the last block.
//
// Math: with r = eps/(1-eps),
//   gate = sigmoid(2(ln r + w)) = r^2 / (r^2 + e^{-2w})
// ---------------------------------------------------------------------------
__global__ void gate_kernel(const float* __restrict__ x,
                            const void* __restrict__ ei,
                            const float* __restrict__ noise,
                            int E, int N, unsigned int k) {
    __shared__ unsigned int sh[2048];
    __shared__ unsigned int scanBuf[256];
    __shared__ unsigned int resSel, resK;
    __shared__ unsigned int isLast;

    for (int i = threadIdx.x; i < 2048; i += blockDim.x) sh[i] = 0u;

    // zero rowsum using the grid's surplus parallelism (consumed only by scatter)
    int gtid = blockIdx.x * blockDim.x + threadIdx.x;
    for (int i = gtid; i < N; i += gridDim.x * blockDim.x) g_rowsum[i] = 0.0f;
    __syncthreads();

    const int is32 = g_idx32;
    const int lane = threadIdx.x & 31;
    const int sub  = lane >> 3;        // edge slot within warp (0..3)
    const int sl   = lane & 7;         // lane within 8-lane group
    const int warpId = gtid >> 5;
    const int nwarps = (gridDim.x * blockDim.x) >> 5;

    for (int base = warpId << 2; base < E; base += nwarps << 2) {
        int e = base + sub;
        bool valid = (e < E);
        int ec = valid ? e : (E - 1);            // clamp for safe loads
        int r = edge_idx(ei, is32, ec);
        int c = edge_idx(ei, is32, (long long)E + ec);
        const float4* ra = (const float4*)(x + ((long long)r << 7));
        const float4* rb = (const float4*)(x + ((long long)c << 7));
        float4 a0 = __ldg(ra + sl);
        float4 a1 = __ldg(ra + sl + 8);
        float4 a2 = __ldg(ra + sl + 16);
        float4 a3 = __ldg(ra + sl + 24);
        float4 b0 = __ldg(rb + sl);
        float4 b1 = __ldg(rb + sl + 8);
        float4 b2 = __ldg(rb + sl + 16);
        float4 b3 = __ldg(rb + sl + 24);

        float v = a0.x * b0.x;
        v = fmaf(a0.y, b0.y, v); v = fmaf(a0.z, b0.z, v); v = fmaf(a0.w, b0.w, v);
        v = fmaf(a1.x, b1.x, v); v = fmaf(a1.y, b1.y, v); v = fmaf(a1.z, b1.z, v); v = fmaf(a1.w, b1.w, v);
        v = fmaf(a2.x, b2.x, v); v = fmaf(a2.y, b2.y, v); v = fmaf(a2.z, b2.z, v); v = fmaf(a2.w, b2.w, v);
        v = fmaf(a3.x, b3.x, v); v = fmaf(a3.y, b3.y, v); v = fmaf(a3.z, b3.z, v); v = fmaf(a3.w, b3.w, v);

        v += __shfl_xor_sync(0xffffffffu, v, 1);
        v += __shfl_xor_sync(0xffffffffu, v, 2);
        v += __shfl_xor_sync(0xffffffffu, v, 4);

        if (sl == 0 && valid) {
            float nz  = __ldg(noise + e);
            float eps = fmaf(-0.9998f, nz, 0.9999f);
            float rr  = __fdividef(eps, 1.0f - eps);
            float r2  = rr * rr;
            float ex  = __expf(-2.0f * v);
            float gate = r2 / (r2 + ex);
            g_gate[e] = gate;
            atomicAdd(&sh[__float_as_uint(gate) >> 21], 1u);
        }
    }
    __syncthreads();
    for (int i = threadIdx.x; i < 2048; i += blockDim.x)
        if (sh[i]) atomicAdd(&g_h1[i], sh[i]);

    // --- fused level-1 select: last block to finish scans g_h1 ---
    __threadfence();
    if (threadIdx.x == 0) {
        unsigned int d = atomicAdd(&g_done1, 1u);
        isLast = (d == gridDim.x - 1) ? 1u : 0u;
    }
    __syncthreads();
    if (isLast) {
        __threadfence();
        for (int i = threadIdx.x; i < 2048; i += blockDim.x)
            sh[i] = __ldcg(&g_h1[i]);       // L2-only loads (bypass stale L1)
        __syncthreads();
        block_suffix_select(sh, 2048, k, scanBuf, &resSel, &resK);
        if (threadIdx.x == 0) { g_sel1 = resSel; g_kRem = resK; }
    }
}

// ---------------------------------------------------------------------------
// K2: compact edges in the sel1 bin (values only), then last block performs
// both remaining select levels entirely in shared memory.
// ---------------------------------------------------------------------------
__global__ void compact_kernel(int E) {
    __shared__ unsigned int hist[2048];
    __shared__ unsigned int scanBuf[256];
    __shared__ unsigned int resSel, resK;
    __shared__ unsigned int isLast;

    const unsigned int sel1 = g_sel1;
    int idx = blockIdx.x * blockDim.x + threadIdx.x;
    int stride = gridDim.x * blockDim.x;
    int nv = E >> 2;
    const float4* g4 = (const float4*)g_gate;

    for (int i = idx; i < nv; i += stride) {
        float4 g = g4[i];
        unsigned int u;
        u = __float_as_uint(g.x); if ((u >> 21) == sel1) g_cand[atomicAdd(&g_candCnt, 1u)] = u;
        u = __float_as_uint(g.y); if ((u >> 21) == sel1) g_cand[atomicAdd(&g_candCnt, 1u)] = u;
        u = __float_as_uint(g.z); if ((u >> 21) == sel1) g_cand[atomicAdd(&g_candCnt, 1u)] = u;
        u = __float_as_uint(g.w); if ((u >> 21) == sel1) g_cand[atomicAdd(&g_candCnt, 1u)] = u;
    }
    for (int e = (nv << 2) + idx; e < E; e += stride) {
        unsigned int u = __float_as_uint(g_gate[e]);
        if ((u >> 21) == sel1) g_cand[atomicAdd(&g_candCnt, 1u)] = u;
    }

    __threadfence();
    if (threadIdx.x == 0) {
        unsigned int d = atomicAdd(&g_done2, 1u);
        isLast = (d == gridDim.x - 1) ? 1u : 0u;
    }
    __syncthreads();
    if (!isLast) return;
    __threadfence();

    const unsigned int cnt  = __ldcg(&g_candCnt);
    const unsigned int kRem = g_kRem;

    // level 2: bits [10,21)
    for (int i = threadIdx.x; i < 2048; i += blockDim.x) hist[i] = 0u;
    __syncthreads();
    for (unsigned int i = threadIdx.x; i < cnt; i += blockDim.x)
        atomicAdd(&hist[(__ldcg(&g_cand[i]) >> 10) & 0x7FFu], 1u);
    __syncthreads();
    block_suffix_select(hist, 2048, kRem, scanBuf, &resSel, &resK);
    const unsigned int sel2  = resSel;
    const unsigned int kRem2 = resK;
    __syncthreads();

    // level 3: bits [0,10)
    for (int i = threadIdx.x; i < 1024; i += blockDim.x) hist[i] = 0u;
    __syncthreads();
    for (unsigned int i = threadIdx.x; i < cnt; i += blockDim.x) {
        unsigned int u = __ldcg(&g_cand[i]);
        if (((u >> 10) & 0x7FFu) == sel2) atomicAdd(&hist[u & 0x3FFu], 1u);
    }
    __syncthreads();
    block_suffix_select(hist, 1024, kRem2, scanBuf, &resSel, &resK);
    if (threadIdx.x == 0)
        g_uT = (sel1 << 21) | (sel2 << 10) | resSel;
}

// ---------------------------------------------------------------------------
// K3: scatter rowsum for kept edges (vectorized, 4 edges/thread).
// Does NOT modify g_gate — out_kernel re-derives the mask from g_uT.
// ---------------------------------------------------------------------------
__global__ void scatter_kernel(const void* __restrict__ ei, int E) {
    const unsigned int uT = g_uT;
    const int is32 = g_idx32;
    int idx = blockIdx.x * blockDim.x + threadIdx.x;
    int stride = gridDim.x * blockDim.x;
    int nv = E >> 2;
    const float4* g4 = (const float4*)g_gate;

    for (int i = idx; i < nv; i += stride) {
        float4 g = g4[i];
        int r[4];
        if (is32) {
            int4 ri = __ldg((const int4*)ei + i);
            r[0] = ri.x; r[1] = ri.y; r[2] = ri.z; r[3] = ri.w;
        } else {
            longlong2 ra = __ldg((const longlong2*)ei + 2 * i);
            longlong2 rb = __ldg((const longlong2*)ei + 2 * i + 1);
            r[0] = (int)ra.x; r[1] = (int)ra.y; r[2] = (int)rb.x; r[3] = (int)rb.y;
        }
        float gv[4] = {g.x, g.y, g.z, g.w};
        #pragma unroll
        for (int j = 0; j < 4; j++) {
            if (__float_as_uint(gv[j]) >= uT && gv[j] != 0.0f)
                atomicAdd(&g_rowsum[r[j]], gv[j]);
        }
    }
    for (int e = (nv << 2) + idx; e < E; e += stride) {
        float gate = g_gate[e];
        if (__float_as_uint(gate) >= uT && gate != 0.0f)
            atomicAdd(&g_rowsum[edge_idx(ei, is32, e)], gate);
    }
}

// ---------------------------------------------------------------------------
// K4: symmetric degree normalization -> output (vectorized, 4 edges/thread)
// ---------------------------------------------------------------------------
__device__ __forceinline__ float dinvf(float rs) {
    if (rs > 0.0f) return fminf(rsqrtf(rs), 10.0f);
    return 10.0f;
}

__global__ void out_kernel(const void* __restrict__ ei,
                           float* __restrict__ out, int E) {
    const unsigned int uT = g_uT;
    const int is32 = g_idx32;
    int idx = blockIdx.x * blockDim.x + threadIdx.x;
    int stride = gridDim.x * blockDim.x;
    int nv = E >> 2;
    const float4* g4 = (const float4*)g_gate;
    float4* o4 = (float4*)out;
    const long long co = (long long)E;  // col offset in elements

    for (int i = idx; i < nv; i += stride) {
        float4 g = g4[i];
        float gv[4] = {g.x, g.y, g.z, g.w};
        float ov[4];
        int r[4], c[4];
        if (is32) {
            int4 ri = __ldg((const int4*)ei + i);
            r[0] = ri.x; r[1] = ri.y; r[2] = ri.z; r[3] = ri.w;
            const int* cp = (const int*)ei + co;
            int4 ci = __ldg((const int4*)cp + i);
            c[0] = ci.x; c[1] = ci.y; c[2] = ci.z; c[3] = ci.w;
        } else {
            longlong2 ra = __ldg((const longlong2*)ei + 2 * i);
            longlong2 rb = __ldg((const longlong2*)ei + 2 * i + 1);
            r[0] = (int)ra.x; r[1] = (int)ra.y; r[2] = (int)rb.x; r[3] = (int)rb.y;
            const long long* cp = (const long long*)ei + co;
            longlong2 ca = __ldg((const longlong2*)cp + 2 * i);
            longlong2 cb = __ldg((const longlong2*)cp + 2 * i + 1);
            c[0] = (int)ca.x; c[1] = (int)ca.y; c[2] = (int)cb.x; c[3] = (int)cb.y;
        }
        #pragma unroll
        for (int j = 0; j < 4; j++) {
            float v = 0.0f;
            if (__float_as_uint(gv[j]) >= uT && gv[j] != 0.0f) {
                float dr = dinvf(g_rowsum[r[j]]);
                float dc = dinvf(g_rowsum[c[j]]);
                v = gv[j] * dr * dc;
            }
            ov[j] = v;
        }
        o4[i] = make_float4(ov[0], ov[1], ov[2], ov[3]);
    }
    for (int e = (nv << 2) + idx; e < E; e += stride) {
        float g = g_gate[e];
        float v = 0.0f;
        if (__float_as_uint(g) >= uT && g != 0.0f) {
            float dr = dinvf(g_rowsum[edge_idx(ei, is32, e)]);
            float dc = dinvf(g_rowsum[edge_idx(ei, is32, co + e)]);
            v = g * dr * dc;
        }
        out[e] = v;
    }
}

// ---------------------------------------------------------------------------
// Launcher: 5 launches (was 9)
// ---------------------------------------------------------------------------
extern "C" void kernel_launch(void* const* d_in, const int* in_sizes, int n_in,
                              void* d_out, int out_size) {
    const float* x     = (const float*)d_in[0];
    const void*  ei    = d_in[1];
    const float* noise = (const float*)d_in[2];
    float*       out   = (float*)d_out;

    int E = in_sizes[2];
    int N = in_sizes[0] / H_DIM;

    unsigned int k = (unsigned int)((double)E * 0.8);  // int(E * KEEP_FRAC)

    init_kernel<<<8, 256>>>(ei, N);
    gate_kernel<<<1184, 256>>>(x, ei, noise, E, N, k);
    int vBlocks = ((E >> 2) + 255) / 256;
    compact_kernel<<<vBlocks, 256>>>(E);
    scatter_kernel<<<vBlocks, 256>>>(ei, E);
    out_kernel<<<vBlocks, 256>>>(ei, out, E);
}

// round 13
// speedup vs baseline: 1.0813x; 1.0813x over previous
#include <cuda_runtime.h>

// Problem constants (shapes fixed by the dataset).
#define H_DIM 128
#define E_MAX 625000
#define N_MAX 100096

// Scratch (device globals — no allocations allowed).
__device__ __align__(16) float g_gate[E_MAX];
__device__ float        g_rowsum[N_MAX];
__device__ unsigned int g_h1[2048];
__device__ unsigned int g_cand[E_MAX];     // gate-bit patterns in the sel1 bin
__device__ unsigned int g_candCnt;
__device__ unsigned int g_sel1, g_kRem;
__device__ unsigned int g_uT;              // final 32-bit keep threshold
__device__ int          g_idx32;           // 1 if edge_index is int32, 0 if int64

// Index fetch that works for either dtype (uniform branch on device flag).
__device__ __forceinline__ int edge_idx(const void* ei, int is32, long long pos) {
    if (is32) return ((const int*)ei)[pos];
    return (int)(((const long long*)ei)[pos]);
}

// ---------------------------------------------------------------------------
// Block-wide (256 threads) descending radix select over B bins (B = 256*chunk,
// chunk <= 8). Finds bin containing the k-th largest (counting from the top
// bin down); writes sel & residual k. hist may be global or shared.
// ---------------------------------------------------------------------------
__device__ void block_suffix_select(const unsigned int* hist, int B,
                                    unsigned int k,
                                    unsigned int* scan,          // smem [256]
                                    volatile unsigned int* outSel,
                                    volatile unsigned int* outK) {
    int t = threadIdx.x;
    int chunk = B >> 8;
    unsigned int loc[8];
    unsigned int s = 0;
    for (int j = 0; j < chunk; j++) { loc[j] = hist[t * chunk + j]; s += loc[j]; }
    scan[t] = s;
    __syncthreads();
    // inclusive suffix scan over 256 chunk-sums
    for (int off = 1; off < 256; off <<= 1) {
        unsigned int v   = scan[t];
        unsigned int add = (t + off < 256) ? scan[t + off] : 0u;
        __syncthreads();
        scan[t] = v + add;
        __syncthreads();
    }
    unsigned int run = (t + 1 < 256) ? scan[t + 1] : 0u;   // suffix after my chunk
    for (int j = chunk - 1; j >= 0; j--) {
        unsigned int nxt = run + loc[j];
        if (run < k && nxt >= k) {          // exactly one (t,j) straddles k
            *outSel = (unsigned int)(t * chunk + j);
            *outK   = k - run;
        }
        run = nxt;
    }
    __syncthreads();
}

// ---------------------------------------------------------------------------
// K0: zero rowsum + h1 + counters (graph replays reuse state); detect dtype.
// int32 read as int64 gives idx0 + idx1*2^32, out of [0,N) w.p. ~1 per sample.
// ---------------------------------------------------------------------------
__global__ void init_kernel(const void* ei, int N) {
    int i = blockIdx.x * blockDim.x + threadIdx.x;
    if (i < N)    g_rowsum[i] = 0.0f;
    if (i < 2048) g_h1[i] = 0u;
    if (i == 0)   g_candCnt = 0u;

    if (blockIdx.x == 0) {               // block-uniform branch: sync is legal
        const long long* p = (const long long*)ei;
        int bad = 0;
        for (int j = threadIdx.x; j < 1024; j += blockDim.x) {
            long long v = p[j];
            if (v < 0 || v >= (long long)N) bad = 1;
        }
        int any = __syncthreads_or(bad);
        if (threadIdx.x == 0) g_idx32 = any ? 1 : 0;
    }
}

// ---------------------------------------------------------------------------
// K1: gate computation, 8 lanes per edge (4 edges/warp), + level-1 histogram.
// (Identical to the 82.0µs version — kept pure.)
//
// Math: with r = eps/(1-eps),
//   gate = sigmoid(2(ln r + w)) = r^2 / (r^2 + e^{-2w})
// ---------------------------------------------------------------------------
__global__ void gate_kernel(const float* __restrict__ x,
                            const void* __restrict__ ei,
                            const float* __restrict__ noise,
                            int E) {
    __shared__ unsigned int sh[2048];
    for (int i = threadIdx.x; i < 2048; i += blockDim.x) sh[i] = 0u;
    __syncthreads();

    const int is32 = g_idx32;
    const int lane = threadIdx.x & 31;
    const int sub  = lane >> 3;        // edge slot within warp (0..3)
    const int sl   = lane & 7;         // lane within 8-lane group
    const int warpId = (blockIdx.x * blockDim.x + threadIdx.x) >> 5;
    const int nwarps = (gridDim.x * blockDim.x) >> 5;

    for (int base = warpId << 2; base < E; base += nwarps << 2) {
        int e = base + sub;
        bool valid = (e < E);
        int ec = valid ? e : (E - 1);            // clamp for safe loads
        int r = edge_idx(ei, is32, ec);
        int c = edge_idx(ei, is32, (long long)E + ec);
        const float4* ra = (const float4*)(x + ((long long)r << 7));
        const float4* rb = (const float4*)(x + ((long long)c << 7));
        float4 a0 = __ldg(ra + sl);
        float4 a1 = __ldg(ra + sl + 8);
        float4 a2 = __ldg(ra + sl + 16);
        float4 a3 = __ldg(ra + sl + 24);
        float4 b0 = __ldg(rb + sl);
        float4 b1 = __ldg(rb + sl + 8);
        float4 b2 = __ldg(rb + sl + 16);
        float4 b3 = __ldg(rb + sl + 24);

        float v = a0.x * b0.x;
        v = fmaf(a0.y, b0.y, v); v = fmaf(a0.z, b0.z, v); v = fmaf(a0.w, b0.w, v);
        v = fmaf(a1.x, b1.x, v); v = fmaf(a1.y, b1.y, v); v = fmaf(a1.z, b1.z, v); v = fmaf(a1.w, b1.w, v);
        v = fmaf(a2.x, b2.x, v); v = fmaf(a2.y, b2.y, v); v = fmaf(a2.z, b2.z, v); v = fmaf(a2.w, b2.w, v);
        v = fmaf(a3.x, b3.x, v); v = fmaf(a3.y, b3.y, v); v = fmaf(a3.z, b3.z, v); v = fmaf(a3.w, b3.w, v);

        v += __shfl_xor_sync(0xffffffffu, v, 1);
        v += __shfl_xor_sync(0xffffffffu, v, 2);
        v += __shfl_xor_sync(0xffffffffu, v, 4);

        if (sl == 0 && valid) {
            float nz  = __ldg(noise + e);
            float eps = fmaf(-0.9998f, nz, 0.9999f);
            float rr  = __fdividef(eps, 1.0f - eps);
            float r2  = rr * rr;
            float ex  = __expf(-2.0f * v);
            float gate = r2 / (r2 + ex);
            g_gate[e] = gate;
            atomicAdd(&sh[__float_as_uint(gate) >> 21], 1u);
        }
    }
    __syncthreads();
    for (int i = threadIdx.x; i < 2048; i += blockDim.x)
        if (sh[i]) atomicAdd(&g_h1[i], sh[i]);
}

// ---------------------------------------------------------------------------
// K2: level-1 select over g_h1 (single block; kernel boundary = global fence)
// ---------------------------------------------------------------------------
__global__ void select1_kernel(unsigned int k) {
    __shared__ unsigned int scanBuf[256];
    __shared__ unsigned int resSel, resK;
    block_suffix_select(g_h1, 2048, k, scanBuf, &resSel, &resK);
    if (threadIdx.x == 0) { g_sel1 = resSel; g_kRem = resK; }
}

// ---------------------------------------------------------------------------
// K3: compact gate-bit patterns falling in the sel1 bin (~1/2048 of edges)
// ---------------------------------------------------------------------------
__global__ void compact_kernel(int E) {
    const unsigned int sel1 = g_sel1;
    int idx = blockIdx.x * blockDim.x + threadIdx.x;
    int stride = gridDim.x * blockDim.x;
    int nv = E >> 2;
    const float4* g4 = (const float4*)g_gate;

    for (int i = idx; i < nv; i += stride) {
        float4 g = g4[i];
        unsigned int u;
        u = __float_as_uint(g.x); if ((u >> 21) == sel1) g_cand[atomicAdd(&g_candCnt, 1u)] = u;
        u = __float_as_uint(g.y); if ((u >> 21) == sel1) g_cand[atomicAdd(&g_candCnt, 1u)] = u;
        u = __float_as_uint(g.z); if ((u >> 21) == sel1) g_cand[atomicAdd(&g_candCnt, 1u)] = u;
        u = __float_as_uint(g.w); if ((u >> 21) == sel1) g_cand[atomicAdd(&g_candCnt, 1u)] = u;
    }
    for (int e = (nv << 2) + idx; e < E; e += stride) {
        unsigned int u = __float_as_uint(g_gate[e]);
        if ((u >> 21) == sel1) g_cand[atomicAdd(&g_candCnt, 1u)] = u;
    }
}

// ---------------------------------------------------------------------------
// K4: levels 2+3 select over the compacted candidates (single block, smem)
// ---------------------------------------------------------------------------
__global__ void select23_kernel() {
    __shared__ unsigned int hist[2048];
    __shared__ unsigned int scanBuf[256];
    __shared__ unsigned int resSel, resK;

    const unsigned int sel1 = g_sel1;
    const unsigned int cnt  = g_candCnt;
    const unsigned int kRem = g_kRem;

    // level 2: bits [10,21)
    for (int i = threadIdx.x; i < 2048; i += blockDim.x) hist[i] = 0u;
    __syncthreads();
    for (unsigned int i = threadIdx.x; i < cnt; i += blockDim.x)
        atomicAdd(&hist[(g_cand[i] >> 10) & 0x7FFu], 1u);
    __syncthreads();
    block_suffix_select(hist, 2048, kRem, scanBuf, &resSel, &resK);
    const unsigned int sel2  = resSel;
    const unsigned int kRem2 = resK;
    __syncthreads();

    // level 3: bits [0,10)
    for (int i = threadIdx.x; i < 1024; i += blockDim.x) hist[i] = 0u;
    __syncthreads();
    for (unsigned int i = threadIdx.x; i < cnt; i += blockDim.x) {
        unsigned int u = g_cand[i];
        if (((u >> 10) & 0x7FFu) == sel2) atomicAdd(&hist[u & 0x3FFu], 1u);
    }
    __syncthreads();
    block_suffix_select(hist, 1024, kRem2, scanBuf, &resSel, &resK);
    if (threadIdx.x == 0)
        g_uT = (sel1 << 21) | (sel2 << 10) | resSel;
}

// ---------------------------------------------------------------------------
// K5: scatter rowsum for kept edges (vectorized, 4 edges/thread).
// Does NOT modify g_gate — out_kernel re-derives the mask from g_uT.
// ---------------------------------------------------------------------------
__global__ void scatter_kernel(const void* __restrict__ ei, int E) {
    const unsigned int uT = g_uT;
    const int is32 = g_idx32;
    int idx = blockIdx.x * blockDim.x + threadIdx.x;
    int stride = gridDim.x * blockDim.x;
    int nv = E >> 2;
    const float4* g4 = (const float4*)g_gate;

    for (int i = idx; i < nv; i += stride) {
        float4 g = g4[i];
        int r[4];
        if (is32) {
            int4 ri = __ldg((const int4*)ei + i);
            r[0] = ri.x; r[1] = ri.y; r[2] = ri.z; r[3] = ri.w;
        } else {
            longlong2 ra = __ldg((const longlong2*)ei + 2 * i);
            longlong2 rb = __ldg((const longlong2*)ei + 2 * i + 1);
            r[0] = (int)ra.x; r[1] = (int)ra.y; r[2] = (int)rb.x; r[3] = (int)rb.y;
        }
        float gv[4] = {g.x, g.y, g.z, g.w};
        #pragma unroll
        for (int j = 0; j < 4; j++) {
            if (__float_as_uint(gv[j]) >= uT && gv[j] != 0.0f)
                atomicAdd(&g_rowsum[r[j]], gv[j]);
        }
    }
    for (int e = (nv << 2) + idx; e < E; e += stride) {
        float gate = g_gate[e];
        if (__float_as_uint(gate) >= uT && gate != 0.0f)
            atomicAdd(&g_rowsum[edge_idx(ei, is32, e)], gate);
    }
}

// ---------------------------------------------------------------------------
// K6: symmetric degree normalization -> output (vectorized, 4 edges/thread)
// ---------------------------------------------------------------------------
__device__ __forceinline__ float dinvf(float rs) {
    if (rs > 0.0f) return fminf(rsqrtf(rs), 10.0f);
    return 10.0f;
}

__global__ void out_kernel(const void* __restrict__ ei,
                           float* __restrict__ out, int E) {
    const unsigned int uT = g_uT;
    const int is32 = g_idx32;
    int idx = blockIdx.x * blockDim.x + threadIdx.x;
    int stride = gridDim.x * blockDim.x;
    int nv = E >> 2;
    const float4* g4 = (const float4*)g_gate;
    float4* o4 = (float4*)out;
    const long long co = (long long)E;  // col offset in elements

    for (int i = idx; i < nv; i += stride) {
        float4 g = g4[i];
        float gv[4] = {g.x, g.y, g.z, g.w};
        float ov[4];
        int r[4], c[4];
        if (is32) {
            int4 ri = __ldg((const int4*)ei + i);
            r[0] = ri.x; r[1] = ri.y; r[2] = ri.z; r[3] = ri.w;
            const int* cp = (const int*)ei + co;
            int4 ci = __ldg((const int4*)cp + i);
            c[0] = ci.x; c[1] = ci.y; c[2] = ci.z; c[3] = ci.w;
        } else {
            longlong2 ra = __ldg((const longlong2*)ei + 2 * i);
            longlong2 rb = __ldg((const longlong2*)ei + 2 * i + 1);
            r[0] = (int)ra.x; r[1] = (int)ra.y; r[2] = (int)rb.x; r[3] = (int)rb.y;
            const long long* cp = (const long long*)ei + co;
            longlong2 ca = __ldg((const longlong2*)cp + 2 * i);
            longlong2 cb = __ldg((const longlong2*)cp + 2 * i + 1);
            c[0] = (int)ca.x; c[1] = (int)ca.y; c[2] = (int)cb.x; c[3] = (int)cb.y;
        }
        #pragma unroll
        for (int j = 0; j < 4; j++) {
            float v = 0.0f;
            if (__float_as_uint(gv[j]) >= uT && gv[j] != 0.0f) {
                float dr = dinvf(g_rowsum[r[j]]);
                float dc = dinvf(g_rowsum[c[j]]);
                v = gv[j] * dr * dc;
            }
            ov[j] = v;
        }
        o4[i] = make_float4(ov[0], ov[1], ov[2], ov[3]);
    }
    for (int e = (nv << 2) + idx; e < E; e += stride) {
        float g = g_gate[e];
        float v = 0.0f;
        if (__float_as_uint(g) >= uT && g != 0.0f) {
            float dr = dinvf(g_rowsum[edge_idx(ei, is32, e)]);
            float dc = dinvf(g_rowsum[edge_idx(ei, is32, co + e)]);
            v = g * dr * dc;
        }
        out[e] = v;
    }
}

// ---------------------------------------------------------------------------
// Launcher: 7 launches
// ---------------------------------------------------------------------------
extern "C" void kernel_launch(void* const* d_in, const int* in_sizes, int n_in,
                              void* d_out, int out_size) {
    const float* x     = (const float*)d_in[0];
    const void*  ei    = d_in[1];
    const float* noise = (const float*)d_in[2];
    float*       out   = (float*)d_out;

    int E = in_sizes[2];
    int N = in_sizes[0] / H_DIM;

    unsigned int k = (unsigned int)((double)E * 0.8);  // int(E * KEEP_FRAC)

    int initThreads = (N > 2048 ? N : 2048);
    init_kernel<<<(initThreads + 255) / 256, 256>>>(ei, N);

    gate_kernel<<<1184, 256>>>(x, ei, noise, E);
    select1_kernel<<<1, 256>>>(k);

    int vBlocks = ((E >> 2) + 255) / 256;
    compact_kernel<<<vBlocks, 256>>>(E);
    select23_kernel<<<1, 256>>>();
    scatter_kernel<<<vBlocks, 256>>>(ei, E);
    out_kernel<<<vBlocks, 256>>>(ei, out, E);
}